// round 6
// baseline (speedup 1.0000x reference)
#include <cuda_runtime.h>
#include <cuda_bf16.h>

// ---------------- problem constants ----------------
#define H_IMG   2048
#define W_IMG   2048
#define C_IMG   3
#define RAD     5
#define NITER   10
#define PH      (H_IMG + 2*RAD)   // 2058
#define PW      (W_IMG + 2*RAD)   // 2058

// Guarded buffer layout: interior pixel (y,x) lives at row y+GY, col x+GX.
// Guard bands stay zero so the iteration kernel loads float4 with NO bounds checks.
#define GY      8
#define GX      8
#define PROWS   2104              // 8 top + 2058 + 38 bottom guard rows
#define PITCH   2208              // 8 left + 2058 + 142 right guard cols
#define PLANE   (PROWS * PITCH)
#define BUFSZ   (C_IMG * PLANE)

__device__ float g_U[2][BUFSZ];

// ---------------- zero buffer 1 entirely (interior overwritten by iter 0) ----
__global__ void swf_zero1() {
    float4* p = (float4*)g_U[1];
    const float4 z = make_float4(0.f, 0.f, 0.f, 0.f);
    int n = BUFSZ / 4;
    for (int i = blockIdx.x * blockDim.x + threadIdx.x; i < n;
         i += gridDim.x * blockDim.x)
        p[i] = z;
}

// ---------------- pad: full-plane write of U[0] (guards = 0, interior = edge-replicated img)
__global__ void swf_pad(const float* __restrict__ img) {
    int total = C_IMG * PROWS * PITCH;
    for (int i = blockIdx.x * blockDim.x + threadIdx.x; i < total;
         i += gridDim.x * blockDim.x) {
        int col = i % PITCH;
        int t   = i / PITCH;
        int row = t % PROWS;
        int c   = t / PROWS;
        float v = 0.0f;
        int y = row - GY, x = col - GX;
        if (y >= 0 && y < PH && x >= 0 && x < PW) {
            int sy = y - RAD; sy = sy < 0 ? 0 : (sy > H_IMG - 1 ? H_IMG - 1 : sy);
            int sx = x - RAD; sx = sx < 0 ? 0 : (sx > W_IMG - 1 ? W_IMG - 1 : sx);
            v = img[(sy * W_IMG + sx) * C_IMG + c];
        }
        g_U[0][c * PLANE + row * PITCH + col] = v;
    }
}

// ---------------- one side-window iteration ----------------
#define TH 32
#define TW 128
#define TROWS (TH + 2*RAD)        // 42
#define TCOLS 144                 // 36 float4
#define TC4   (TCOLS/4)           // 36
#define NF4   (TROWS * TC4)       // 1512
#define H6W   136

__global__ __launch_bounds__(256)
void swf_iter(int s) {
    const float* __restrict__ S = g_U[s];
    float* __restrict__ Dst = g_U[s ^ 1];

    __shared__ float tile[TROWS * TCOLS];   // 42*144 = 6048 floats
    __shared__ float h6[TROWS * H6W];       // 42*136 = 5712 floats

    const int c  = blockIdx.z;
    const int x0 = blockIdx.x * TW;
    const int y0 = blockIdx.y * TH;
    const int t  = threadIdx.x;             // 0..255
    const float* __restrict__ Sp = S + c * PLANE;
    float* __restrict__ Dp = Dst + c * PLANE;

    // ---- Stage 1: unconditional float4 tile load (guards supply zeros) ----
    // tile col 0 <-> buffer col x0 (gx = x0-8); tile row r <-> buffer row y0+3+r.
    {
        const float4* __restrict__ Sp4 =
            (const float4*)(Sp + (y0 + 3) * PITCH + x0);
        float4* tile4 = (float4*)tile;
        #pragma unroll
        for (int k = 0; k < 6; k++) {
            int idx = t + k * 256;
            if (idx < NF4) {
                int r  = idx / TC4;
                int c4 = idx - r * TC4;
                tile4[r * TC4 + c4] = Sp4[r * (PITCH / 4) + c4];
            }
        }
    }
    __syncthreads();

    // ---- Stage 2: horizontal extended 6-sums, per-thread sliding windows ----
    // h6[r][cc] = sum tile[r][cc+3 .. cc+8]
    if (t < 252) {
        int r   = t / 6;
        int seg = t - r * 6;                 // 0..5
        int sx  = seg * 23;
        int ex  = sx + 23; if (ex > 133) ex = 133;
        const float* trow = &tile[r * TCOLS];
        float* hrow = &h6[r * H6W];
        float sum = trow[sx + 3] + trow[sx + 4] + trow[sx + 5]
                  + trow[sx + 6] + trow[sx + 7] + trow[sx + 8];
        hrow[sx] = sum;
        for (int cc = sx + 1; cc < ex; cc++) {
            sum += trow[cc + 8] - trow[cc + 2];
            hrow[cc] = sum;
        }
    }
    __syncthreads();

    // ---- Stage 3: lead-sum vertical walk ----
    // Per output row ly (local, tile rows ly..ly+10, center ly+5), with
    // lead index j = ly+10:
    //   A(j) = sum_{k=j-5..j} HL(k)  -> dL = A(j), uL = A(j-5)
    //   B(j) over HR                 -> dR, uR
    //   C6(j) over center col        -> only feeds Dw
    //   Dw(j) = A+B-C6               -> dF = Dw(j), uF = Dw(j-5)
    //   fL = uL + dL - HL(j-5), fR = uR + dR - HR(j-5), c0 = Cc(j-5)
    const int lx   = t & 127;
    const int half = t >> 7;
    const int base = half * (TH / 2);       // 0 or 16
    const int gx   = x0 + lx;
    const bool xok = (gx < PW);

    const float i36 = 1.0f / 36.0f;
    const float i66 = 1.0f / 66.0f;

    const float* hp  = h6 + lx;
    const float* hp5 = h6 + lx + 5;
    const float* cp  = tile + lx + 8;

    float rHL[7], rHR[7], rCc[7];
    #pragma unroll
    for (int j = 0; j < 7; j++) {
        int row = base + j;
        rHL[j] = hp[row * H6W];
        rHR[j] = hp5[row * H6W];
        rCc[j] = cp[row * TCOLS];
    }

    // init sums at lead j=5 (rows 0..5)
    float A  = rHL[0] + rHL[1] + rHL[2] + rHL[3] + rHL[4] + rHL[5];
    float B  = rHR[0] + rHR[1] + rHR[2] + rHR[3] + rHR[4] + rHR[5];
    float C6 = rCc[0] + rCc[1] + rCc[2] + rCc[3] + rCc[4] + rCc[5];
    float Dw = A + B - C6;

    float Ah[6], Bh[6], Dh[6];
    Ah[5] = A; Bh[5] = B; Dh[5] = Dw;

    // prologue step j=6 (row already in ring, no load)
    A  += rHL[6] - rHL[0];
    B  += rHR[6] - rHR[0];
    C6 += rCc[6] - rCc[0];
    Dw  = A + B - C6;
    Ah[0] = A; Bh[0] = B; Dh[0] = Dw;

    // prologue steps j=7..9 (load + update, no output)
    #pragma unroll
    for (int j = 7; j <= 9; j++) {
        int row = base + j;
        float nHL = hp[row * H6W];
        float nHR = hp5[row * H6W];
        float nCc = cp[row * TCOLS];
        A  += nHL - rHL[(j - 6) % 7];
        B  += nHR - rHR[(j - 6) % 7];
        C6 += nCc - rCc[(j - 6) % 7];
        rHL[j % 7] = nHL; rHR[j % 7] = nHR; rCc[j % 7] = nCc;
        Dw = A + B - C6;
        Ah[j % 6] = A; Bh[j % 6] = B; Dh[j % 6] = Dw;
    }

    float* Drow = Dp + (y0 + base + GY) * PITCH + gx + GX;

    // main walk: ly = 0..15, lead j = 10+ly
    #pragma unroll
    for (int ly = 0; ly < TH / 2; ly++) {
        const int j = 10 + ly;
        {
            int row = base + j;
            float nHL = hp[row * H6W];
            float nHR = hp5[row * H6W];
            float nCc = cp[row * TCOLS];
            A  += nHL - rHL[(j - 6) % 7];
            B  += nHR - rHR[(j - 6) % 7];
            C6 += nCc - rCc[(j - 6) % 7];
            rHL[j % 7] = nHL; rHR[j % 7] = nHR; rCc[j % 7] = nCc;
            Dw = A + B - C6;
        }

        const float uL = Ah[(j - 5) % 6];
        const float uR = Bh[(j - 5) % 6];
        const float uF = Dh[(j - 5) % 6];
        Ah[j % 6] = A; Bh[j % 6] = B; Dh[j % 6] = Dw;

        const float hL = rHL[(j - 5) % 7];
        const float hR = rHR[(j - 5) % 7];
        const float c0 = rCc[(j - 5) % 7];
        const float nc0 = -c0;

        const float fL = uL + A - hL;
        const float fR = uR + B - hR;

        // deltas, reference order [LL,LR,RL,RR,L*k,R*k,k*L,k*R]
        const float d0 = fmaf(uL, i36, nc0);
        const float d1 = fmaf(uR, i36, nc0);
        const float d2 = fmaf(A,  i36, nc0);
        const float d3 = fmaf(B,  i36, nc0);
        const float d4 = fmaf(uF, i66, nc0);
        const float d5 = fmaf(Dw, i66, nc0);
        const float d6 = fmaf(fL, i66, nc0);
        const float d7 = fmaf(fR, i66, nc0);

        // Tournament argmin, first-min-on-tie.
        float w01 = (fabsf(d1) < fabsf(d0)) ? d1 : d0;
        float a01 = fminf(fabsf(d1), fabsf(d0));
        float w23 = (fabsf(d3) < fabsf(d2)) ? d3 : d2;
        float a23 = fminf(fabsf(d3), fabsf(d2));
        float w45 = (fabsf(d5) < fabsf(d4)) ? d5 : d4;
        float a45 = fminf(fabsf(d5), fabsf(d4));
        float w67 = (fabsf(d7) < fabsf(d6)) ? d7 : d6;
        float a67 = fminf(fabsf(d7), fabsf(d6));

        float w03 = (a23 < a01) ? w23 : w01;
        float a03 = fminf(a23, a01);
        float w47 = (a67 < a45) ? w67 : w45;
        float a47 = fminf(a67, a45);

        float bd = (a47 < a03) ? w47 : w03;

        const int gy = y0 + base + ly;
        if (xok && gy < PH) {
            Drow[ly * PITCH] = c0 + bd;
        }
    }
}

// ---------------- crop planar padded -> HWC output ----------------
__global__ void swf_crop(float* __restrict__ out) {
    int total = H_IMG * W_IMG * C_IMG;
    for (int i = blockIdx.x * blockDim.x + threadIdx.x; i < total;
         i += gridDim.x * blockDim.x) {
        int c = i % C_IMG;
        int t = i / C_IMG;
        int x = t % W_IMG;
        int y = t / W_IMG;
        out[i] = g_U[0][c * PLANE + (y + RAD + GY) * PITCH + (x + RAD + GX)];
    }
}

extern "C" void kernel_launch(void* const* d_in, const int* in_sizes, int n_in,
                              void* d_out, int out_size) {
    const float* img = (const float*)d_in[0];   // (2048,2048,3) f32; d_in[1] hardcoded
    float* out = (float*)d_out;

    swf_zero1<<<2048, 256>>>();
    {
        int total = C_IMG * PROWS * PITCH;
        int blocks = (total + 255) / 256;
        if (blocks > 65535) blocks = 65535;
        swf_pad<<<blocks, 256>>>(img);
    }

    dim3 block(256, 1, 1);
    dim3 grid((PW + TW - 1) / TW, (PH + TH - 1) / TH, C_IMG);
    for (int i = 0; i < NITER; i++) {
        swf_iter<<<grid, block>>>(i & 1);
    }

    {
        int total = H_IMG * W_IMG * C_IMG;
        int blocks = (total + 255) / 256;
        if (blocks > 65535) blocks = 65535;
        swf_crop<<<blocks, 256>>>(out);
    }
}

// round 7
// speedup vs baseline: 1.0477x; 1.0477x over previous
#include <cuda_runtime.h>
#include <cuda_bf16.h>

// ---------------- problem constants ----------------
#define H_IMG   2048
#define W_IMG   2048
#define C_IMG   3
#define RAD     5
#define NITER   10
#define PH      (H_IMG + 2*RAD)   // 2058
#define PW      (W_IMG + 2*RAD)   // 2058

// Guarded buffer layout: interior pixel (y,x) lives at row y+GY, col x+GX.
// Guard bands stay zero so the iteration kernel loads float4 with NO bounds checks.
#define GY      8
#define GX      8
#define PROWS   2104              // 8 top + 2058 + 38 bottom guard rows
#define PITCH   2208              // 8 left + 2058 + 142 right guard cols
#define PLANE   (PROWS * PITCH)
#define BUFSZ   (C_IMG * PLANE)

__device__ float g_U[2][BUFSZ];

// ---------------- zero all guard bands of both buffers ----------------
#define NA (8 * PITCH)
#define NB (38 * PITCH)
#define NL (PH * 8)
#define NR (PH * 142)
#define NGUARD (NA + NB + NL + NR)

__global__ void swf_guard_zero() {
    int plane = blockIdx.y;            // 0..5 : b*3 + c
    int b = plane / 3;
    int c = plane - b * 3;
    float* base = g_U[b] + c * PLANE;
    for (int i = blockIdx.x * blockDim.x + threadIdx.x; i < NGUARD;
         i += gridDim.x * blockDim.x) {
        int row, col, r = i;
        if (r < NA)                { row = r / PITCH;            col = r % PITCH; }
        else if ((r -= NA) < NB)   { row = 2066 + r / PITCH;     col = r % PITCH; }
        else if ((r -= NB) < NL)   { row = GY + r / 8;           col = r % 8; }
        else        { r -= NL;       row = GY + r / 142;          col = 2066 + r % 142; }
        base[row * PITCH + col] = 0.0f;
    }
}

// ---------------- pad (edge replicate) HWC -> planar padded interior ----------------
__global__ void swf_pad(const float* __restrict__ img) {
    int total = C_IMG * PH * PW;
    for (int i = blockIdx.x * blockDim.x + threadIdx.x; i < total;
         i += gridDim.x * blockDim.x) {
        int x = i % PW;
        int t = i / PW;
        int y = t % PH;
        int c = t / PH;
        int sy = y - RAD; sy = sy < 0 ? 0 : (sy > H_IMG - 1 ? H_IMG - 1 : sy);
        int sx = x - RAD; sx = sx < 0 ? 0 : (sx > W_IMG - 1 ? W_IMG - 1 : sx);
        g_U[0][c * PLANE + (y + GY) * PITCH + (x + GX)] =
            img[(sy * W_IMG + sx) * C_IMG + c];
    }
}

// ---------------- one side-window iteration ----------------
// TH=30 so grid = 17 x 69 x 3 = 3519 blocks = 5.94 waves at 4 blocks/SM
// (vs TH=32: 5.60 waves, ~10% tail idle).
#define TH 30
#define TROWS (TH + 2*RAD)        // 40
#define TW 128
#define TCOLS 148                 // 37 float4; bank-friendly stride
#define TC4   (TCOLS/4)           // 37
#define NF4   (TROWS * TC4)       // 1480
#define H6W   136                 // >= 133 used

__global__ __launch_bounds__(256)
void swf_iter(int s) {
    const float* __restrict__ S = g_U[s];
    float* __restrict__ Dst = g_U[s ^ 1];

    __shared__ float tile[TROWS * TCOLS];   // 40*148 floats
    __shared__ float h6[TROWS * H6W];       // 40*136 floats

    const int c  = blockIdx.z;
    const int x0 = blockIdx.x * TW;
    const int y0 = blockIdx.y * TH;
    const int t  = threadIdx.x;             // 0..255
    const float* __restrict__ Sp = S + c * PLANE;
    float* __restrict__ Dp = Dst + c * PLANE;

    // ---- Stage 1: unconditional float4 tile load (guards supply zeros) ----
    // tile col 0 <-> buffer col x0 (gx = x0-8); tile row r <-> buffer row y0+3+r.
    {
        const float4* __restrict__ Sp4 =
            (const float4*)(Sp + (y0 + 3) * PITCH + x0);
        float4* tile4 = (float4*)tile;
        #pragma unroll
        for (int k = 0; k < 6; k++) {
            int idx = t + k * 256;
            if (idx < NF4) {
                int r  = idx / TC4;
                int c4 = idx - r * TC4;
                tile4[r * TC4 + c4] = Sp4[r * (PITCH / 4) + c4];
            }
        }
    }
    __syncthreads();

    // ---- Stage 2: horizontal extended 6-sums, per-thread sliding windows ----
    // h6[r][cc] = sum tile[r][cc+3 .. cc+8]
    if (t < TROWS * 6) {
        int r   = t / 6;
        int seg = t - r * 6;                 // 0..5
        int sx  = seg * 23;
        int ex  = sx + 23; if (ex > 133) ex = 133;
        const float* trow = &tile[r * TCOLS];
        float* hrow = &h6[r * H6W];
        float sum = trow[sx + 3] + trow[sx + 4] + trow[sx + 5]
                  + trow[sx + 6] + trow[sx + 7] + trow[sx + 8];
        hrow[sx] = sum;
        for (int cc = sx + 1; cc < ex; cc++) {
            sum += trow[cc + 8] - trow[cc + 2];
            hrow[cc] = sum;
        }
    }
    __syncthreads();

    // ---- Stage 3: per-thread vertical walk with register ring buffers ----
    const int lx   = t & 127;
    const int half = t >> 7;
    const int base = half * (TH / 2);        // 0 or 15
    const int gx   = x0 + lx;
    const bool xok = (gx < PW);

    const float i36 = 1.0f / 36.0f;
    const float i66 = 1.0f / 66.0f;

    float rHL[12], rHR[12], rC[12];
    #pragma unroll
    for (int i = 0; i < 11; i++) {
        int row = base + i;
        rHL[i] = h6[row * H6W + lx];
        rHR[i] = h6[row * H6W + lx + 5];
        rC[i]  = tile[row * TCOLS + lx + 8];
    }

    float uL = 0.f, uR = 0.f, Vu = 0.f, dL = 0.f, dR = 0.f, Vd = 0.f;
    #pragma unroll
    for (int i = 0; i < 6; i++)  { uL += rHL[i]; uR += rHR[i]; Vu += rC[i]; }
    #pragma unroll
    for (int i = 5; i < 11; i++) { dL += rHL[i]; dR += rHR[i]; Vd += rC[i]; }

    float* Drow = Dp + (y0 + base + GY) * PITCH + gx + GX;

    #pragma unroll
    for (int ly = 0; ly < TH / 2; ly++) {
        if (ly > 0) {
            const int slot = (10 + ly) % 12;
            const int row  = base + 10 + ly;
            float nHL = h6[row * H6W + lx];
            float nHR = h6[row * H6W + lx + 5];
            float nC  = tile[row * TCOLS + lx + 8];
            const int du = (ly - 1) % 12;
            const int au = (5 + ly) % 12;
            const int dd = (4 + ly) % 12;
            uL += rHL[au] - rHL[du];
            uR += rHR[au] - rHR[du];
            Vu += rC[au]  - rC[du];
            dL += nHL - rHL[dd];
            dR += nHR - rHR[dd];
            Vd += nC  - rC[dd];
            rHL[slot] = nHL; rHR[slot] = nHR; rC[slot] = nC;
        }

        const int cs = (5 + ly) % 12;
        const float c0  = rC[cs];
        const float nc0 = -c0;
        const float hL = rHL[cs];
        const float hR = rHR[cs];

        const float uF = uL + uR - Vu;
        const float dF = dL + dR - Vd;
        const float fL = uL + dL - hL;
        const float fR = uR + dR - hR;

        // deltas, reference order [LL,LR,RL,RR,L*k,R*k,k*L,k*R]
        const float d0 = fmaf(uL, i36, nc0);
        const float d1 = fmaf(uR, i36, nc0);
        const float d2 = fmaf(dL, i36, nc0);
        const float d3 = fmaf(dR, i36, nc0);
        const float d4 = fmaf(uF, i66, nc0);
        const float d5 = fmaf(dF, i66, nc0);
        const float d6 = fmaf(fL, i66, nc0);
        const float d7 = fmaf(fR, i66, nc0);

        // Tournament argmin, first-min-on-tie (strict < picks the later element
        // only when strictly smaller; left group indices < right group indices).
        float w01 = (fabsf(d1) < fabsf(d0)) ? d1 : d0;
        float a01 = fminf(fabsf(d1), fabsf(d0));
        float w23 = (fabsf(d3) < fabsf(d2)) ? d3 : d2;
        float a23 = fminf(fabsf(d3), fabsf(d2));
        float w45 = (fabsf(d5) < fabsf(d4)) ? d5 : d4;
        float a45 = fminf(fabsf(d5), fabsf(d4));
        float w67 = (fabsf(d7) < fabsf(d6)) ? d7 : d6;
        float a67 = fminf(fabsf(d7), fabsf(d6));

        float w03 = (a23 < a01) ? w23 : w01;
        float a03 = fminf(a23, a01);
        float w47 = (a67 < a45) ? w67 : w45;
        float a47 = fminf(a67, a45);

        float bd = (a47 < a03) ? w47 : w03;

        const int gy = y0 + base + ly;
        if (xok && gy < PH) {
            Drow[ly * PITCH] = c0 + bd;
        }
    }
}

// ---------------- crop planar padded -> HWC output ----------------
__global__ void swf_crop(float* __restrict__ out) {
    int total = H_IMG * W_IMG * C_IMG;
    for (int i = blockIdx.x * blockDim.x + threadIdx.x; i < total;
         i += gridDim.x * blockDim.x) {
        int c = i % C_IMG;
        int t = i / C_IMG;
        int x = t % W_IMG;
        int y = t / W_IMG;
        out[i] = g_U[0][c * PLANE + (y + RAD + GY) * PITCH + (x + RAD + GX)];
    }
}

extern "C" void kernel_launch(void* const* d_in, const int* in_sizes, int n_in,
                              void* d_out, int out_size) {
    const float* img = (const float*)d_in[0];   // (2048,2048,3) f32; d_in[1] hardcoded
    float* out = (float*)d_out;

    {
        dim3 grid(512, 6, 1);
        swf_guard_zero<<<grid, 256>>>();
    }
    {
        int total = C_IMG * PH * PW;
        int blocks = (total + 255) / 256;
        if (blocks > 65535) blocks = 65535;
        swf_pad<<<blocks, 256>>>(img);
    }

    dim3 block(256, 1, 1);
    dim3 grid((PW + TW - 1) / TW, (PH + TH - 1) / TH, C_IMG);
    for (int i = 0; i < NITER; i++) {
        swf_iter<<<grid, block>>>(i & 1);
    }

    {
        int total = H_IMG * W_IMG * C_IMG;
        int blocks = (total + 255) / 256;
        if (blocks > 65535) blocks = 65535;
        swf_crop<<<blocks, 256>>>(out);
    }
}

// round 8
// speedup vs baseline: 1.1982x; 1.1436x over previous
#include <cuda_runtime.h>
#include <cuda_bf16.h>

// ---------------- problem constants ----------------
#define H_IMG   2048
#define W_IMG   2048
#define C_IMG   3
#define RAD     5
#define NITER   10
#define PH      (H_IMG + 2*RAD)   // 2058
#define PW      (W_IMG + 2*RAD)   // 2058

// Guarded buffer layout: interior pixel (y,x) lives at row y+GY, col x+GX.
// Guard bands stay zero so the iteration kernel loads float4 with NO bounds checks.
#define GY      8
#define GX      8
#define PROWS   2104
#define PITCH   2208
#define PLANE   (PROWS * PITCH)
#define BUFSZ   (C_IMG * PLANE)

__device__ float g_U[2][BUFSZ];

// ---------------- zero all guard bands of both buffers ----------------
#define NA (8 * PITCH)
#define NB (38 * PITCH)
#define NL (PH * 8)
#define NR (PH * 142)
#define NGUARD (NA + NB + NL + NR)

__global__ void swf_guard_zero() {
    int plane = blockIdx.y;            // 0..5 : b*3 + c
    int b = plane / 3;
    int c = plane - b * 3;
    float* base = g_U[b] + c * PLANE;
    for (int i = blockIdx.x * blockDim.x + threadIdx.x; i < NGUARD;
         i += gridDim.x * blockDim.x) {
        int row, col, r = i;
        if (r < NA)                { row = r / PITCH;            col = r % PITCH; }
        else if ((r -= NA) < NB)   { row = 2066 + r / PITCH;     col = r % PITCH; }
        else if ((r -= NB) < NL)   { row = GY + r / 8;           col = r % 8; }
        else        { r -= NL;       row = GY + r / 142;          col = 2066 + r % 142; }
        base[row * PITCH + col] = 0.0f;
    }
}

// ---------------- pad (edge replicate) HWC -> planar padded interior ----------------
__global__ void swf_pad(const float* __restrict__ img) {
    int total = C_IMG * PH * PW;
    for (int i = blockIdx.x * blockDim.x + threadIdx.x; i < total;
         i += gridDim.x * blockDim.x) {
        int x = i % PW;
        int t = i / PW;
        int y = t % PH;
        int c = t / PH;
        int sy = y - RAD; sy = sy < 0 ? 0 : (sy > H_IMG - 1 ? H_IMG - 1 : sy);
        int sx = x - RAD; sx = sx < 0 ? 0 : (sx > W_IMG - 1 ? W_IMG - 1 : sx);
        g_U[0][c * PLANE + (y + GY) * PITCH + (x + GX)] =
            img[(sy * W_IMG + sx) * C_IMG + c];
    }
}

// ---------------- one side-window iteration ----------------
#define TH 30
#define TROWS (TH + 2*RAD)        // 40
#define TW 128
#define TCOLS 148                 // 37 float4; bank-friendly stride
#define TC4   (TCOLS/4)           // 37
#define NF4   (TROWS * TC4)       // 1480
#define H6W   136

// Stage-3 vertical walk with lead sums. FULL=true: no per-row bounds check.
// nvalid used only when FULL=false.
template<bool FULL>
__device__ __forceinline__ void walk(const float* __restrict__ hp,
                                     const float* __restrict__ hp5,
                                     const float* __restrict__ cp,
                                     float* __restrict__ Drow,
                                     int base, bool xok, int nvalid)
{
    const float i36 = 1.0f / 36.0f;
    const float i66 = 1.0f / 66.0f;

    float rHL[7], rHR[7], rCc[7];
    #pragma unroll
    for (int j = 0; j < 7; j++) {
        int row = base + j;
        rHL[j] = hp[row * H6W];
        rHR[j] = hp5[row * H6W];
        rCc[j] = cp[row * TCOLS];
    }

    // lead sums at j=5 (rows 0..5 of this half's window span)
    float A  = rHL[0] + rHL[1] + rHL[2] + rHL[3] + rHL[4] + rHL[5];
    float B  = rHR[0] + rHR[1] + rHR[2] + rHR[3] + rHR[4] + rHR[5];
    float C6 = rCc[0] + rCc[1] + rCc[2] + rCc[3] + rCc[4] + rCc[5];
    float Dw = A + B - C6;

    float Ah[6], Bh[6], Dh[6];
    Ah[5] = A; Bh[5] = B; Dh[5] = Dw;

    // prologue j=6 (row already in ring)
    A  += rHL[6] - rHL[0];
    B  += rHR[6] - rHR[0];
    C6 += rCc[6] - rCc[0];
    Dw  = A + B - C6;
    Ah[0] = A; Bh[0] = B; Dh[0] = Dw;

    // prologue j=7..9
    #pragma unroll
    for (int j = 7; j <= 9; j++) {
        int row = base + j;
        float nHL = hp[row * H6W];
        float nHR = hp5[row * H6W];
        float nCc = cp[row * TCOLS];
        A  += nHL - rHL[(j - 6) % 7];
        B  += nHR - rHR[(j - 6) % 7];
        C6 += nCc - rCc[(j - 6) % 7];
        rHL[j % 7] = nHL; rHR[j % 7] = nHR; rCc[j % 7] = nCc;
        Dw = A + B - C6;
        Ah[j % 6] = A; Bh[j % 6] = B; Dh[j % 6] = Dw;
    }

    // main walk: ly = 0..TH/2-1, lead j = 10+ly
    #pragma unroll
    for (int ly = 0; ly < TH / 2; ly++) {
        const int j = 10 + ly;
        {
            int row = base + j;
            float nHL = hp[row * H6W];
            float nHR = hp5[row * H6W];
            float nCc = cp[row * TCOLS];
            A  += nHL - rHL[(j - 6) % 7];
            B  += nHR - rHR[(j - 6) % 7];
            C6 += nCc - rCc[(j - 6) % 7];
            rHL[j % 7] = nHL; rHR[j % 7] = nHR; rCc[j % 7] = nCc;
            Dw = A + B - C6;
        }

        const float uL = Ah[(j - 5) % 6];
        const float uR = Bh[(j - 5) % 6];
        const float uF = Dh[(j - 5) % 6];
        Ah[j % 6] = A; Bh[j % 6] = B; Dh[j % 6] = Dw;

        const float hL = rHL[(j - 5) % 7];
        const float hR = rHR[(j - 5) % 7];
        const float c0 = rCc[(j - 5) % 7];
        const float nc0 = -c0;

        const float fL = uL + A - hL;
        const float fR = uR + B - hR;

        // deltas, reference order [LL,LR,RL,RR,L*k,R*k,k*L,k*R]
        const float d0 = fmaf(uL, i36, nc0);
        const float d1 = fmaf(uR, i36, nc0);
        const float d2 = fmaf(A,  i36, nc0);
        const float d3 = fmaf(B,  i36, nc0);
        const float d4 = fmaf(uF, i66, nc0);
        const float d5 = fmaf(Dw, i66, nc0);
        const float d6 = fmaf(fL, i66, nc0);
        const float d7 = fmaf(fR, i66, nc0);

        // Tournament argmin, first-min-on-tie.
        float w01 = (fabsf(d1) < fabsf(d0)) ? d1 : d0;
        float a01 = fminf(fabsf(d1), fabsf(d0));
        float w23 = (fabsf(d3) < fabsf(d2)) ? d3 : d2;
        float a23 = fminf(fabsf(d3), fabsf(d2));
        float w45 = (fabsf(d5) < fabsf(d4)) ? d5 : d4;
        float a45 = fminf(fabsf(d5), fabsf(d4));
        float w67 = (fabsf(d7) < fabsf(d6)) ? d7 : d6;
        float a67 = fminf(fabsf(d7), fabsf(d6));

        float w03 = (a23 < a01) ? w23 : w01;
        float a03 = fminf(a23, a01);
        float w47 = (a67 < a45) ? w67 : w45;
        float a47 = fminf(a67, a45);

        float bd = (a47 < a03) ? w47 : w03;

        if (FULL) {
            if (xok) Drow[ly * PITCH] = c0 + bd;
        } else {
            if (xok && ly < nvalid) Drow[ly * PITCH] = c0 + bd;
        }
    }
}

__global__ __launch_bounds__(256)
void swf_iter(int s) {
    const float* __restrict__ S = g_U[s];
    float* __restrict__ Dst = g_U[s ^ 1];

    __shared__ float tile[TROWS * TCOLS];   // 40*148 floats
    __shared__ float h6[TROWS * H6W];       // 40*136 floats

    const int c  = blockIdx.z;
    const int x0 = blockIdx.x * TW;
    const int y0 = blockIdx.y * TH;
    const int t  = threadIdx.x;             // 0..255
    const float* __restrict__ Sp = S + c * PLANE;
    float* __restrict__ Dp = Dst + c * PLANE;

    // ---- Stage 1: unconditional float4 tile load (guards supply zeros) ----
    {
        const float4* __restrict__ Sp4 =
            (const float4*)(Sp + (y0 + 3) * PITCH + x0);
        float4* tile4 = (float4*)tile;
        #pragma unroll
        for (int k = 0; k < 6; k++) {
            int idx = t + k * 256;
            if (idx < NF4) {
                int r  = idx / TC4;
                int c4 = idx - r * TC4;
                tile4[r * TC4 + c4] = Sp4[r * (PITCH / 4) + c4];
            }
        }
    }
    __syncthreads();

    // ---- Stage 2: horizontal extended 6-sums, per-thread sliding windows ----
    if (t < TROWS * 6) {
        int r   = t / 6;
        int seg = t - r * 6;                 // 0..5
        int sx  = seg * 23;
        int ex  = sx + 23; if (ex > 133) ex = 133;
        const float* trow = &tile[r * TCOLS];
        float* hrow = &h6[r * H6W];
        float sum = trow[sx + 3] + trow[sx + 4] + trow[sx + 5]
                  + trow[sx + 6] + trow[sx + 7] + trow[sx + 8];
        hrow[sx] = sum;
        for (int cc = sx + 1; cc < ex; cc++) {
            sum += trow[cc + 8] - trow[cc + 2];
            hrow[cc] = sum;
        }
    }
    __syncthreads();

    // ---- Stage 3 ----
    const int lx   = t & 127;
    const int half = t >> 7;
    const int base = half * (TH / 2);        // 0 or 15
    const int gx   = x0 + lx;
    const bool xok = (gx < PW);

    const float* hp  = h6 + lx;
    const float* hp5 = h6 + lx + 5;
    const float* cp  = tile + lx + 8;
    float* Drow = Dp + (y0 + base + GY) * PITCH + gx + GX;

    const int row0 = y0 + base;              // first output row of this half
    if (row0 + TH / 2 <= PH) {
        walk<true>(hp, hp5, cp, Drow, base, xok, 0);
    } else {
        int nvalid = PH - row0;              // may be <= 0 for fully-oob halves
        walk<false>(hp, hp5, cp, Drow, base, xok, nvalid);
    }
}

// ---------------- crop planar padded -> HWC output ----------------
__global__ void swf_crop(float* __restrict__ out) {
    int total = H_IMG * W_IMG * C_IMG;
    for (int i = blockIdx.x * blockDim.x + threadIdx.x; i < total;
         i += gridDim.x * blockDim.x) {
        int c = i % C_IMG;
        int t = i / C_IMG;
        int x = t % W_IMG;
        int y = t / W_IMG;
        out[i] = g_U[0][c * PLANE + (y + RAD + GY) * PITCH + (x + RAD + GX)];
    }
}

extern "C" void kernel_launch(void* const* d_in, const int* in_sizes, int n_in,
                              void* d_out, int out_size) {
    const float* img = (const float*)d_in[0];   // (2048,2048,3) f32; d_in[1] hardcoded
    float* out = (float*)d_out;

    {
        dim3 grid(512, 6, 1);
        swf_guard_zero<<<grid, 256>>>();
    }
    {
        int total = C_IMG * PH * PW;
        int blocks = (total + 255) / 256;
        if (blocks > 65535) blocks = 65535;
        swf_pad<<<blocks, 256>>>(img);
    }

    dim3 block(256, 1, 1);
    dim3 grid((PW + TW - 1) / TW, (PH + TH - 1) / TH, C_IMG);
    for (int i = 0; i < NITER; i++) {
        swf_iter<<<grid, block>>>(i & 1);
    }

    {
        int total = H_IMG * W_IMG * C_IMG;
        int blocks = (total + 255) / 256;
        if (blocks > 65535) blocks = 65535;
        swf_crop<<<blocks, 256>>>(out);
    }
}

// round 9
// speedup vs baseline: 1.2968x; 1.0824x over previous
#include <cuda_runtime.h>
#include <cuda_bf16.h>

// ---------------- problem constants ----------------
#define H_IMG   2048
#define W_IMG   2048
#define C_IMG   3
#define RAD     5
#define NITER   10
#define PH      (H_IMG + 2*RAD)   // 2058
#define PW      (W_IMG + 2*RAD)   // 2058

// Guarded buffer layout: interior pixel (y,x) lives at row y+GY, col x+GX.
// Guard bands stay zero so the iteration kernel loads float4 with NO bounds checks.
#define GY      8
#define GX      8
#define PROWS   2104
#define PITCH   2208
#define PLANE   (PROWS * PITCH)
#define BUFSZ   (C_IMG * PLANE)

__device__ float g_U[2][BUFSZ];

// ---------------- zero all guard bands of both buffers ----------------
#define NA (8 * PITCH)
#define NB (38 * PITCH)
#define NL (PH * 8)
#define NR (PH * 142)
#define NGUARD (NA + NB + NL + NR)

__global__ void swf_guard_zero() {
    int plane = blockIdx.y;            // 0..5 : b*3 + c
    int b = plane / 3;
    int c = plane - b * 3;
    float* base = g_U[b] + c * PLANE;
    for (int i = blockIdx.x * blockDim.x + threadIdx.x; i < NGUARD;
         i += gridDim.x * blockDim.x) {
        int row, col, r = i;
        if (r < NA)                { row = r / PITCH;            col = r % PITCH; }
        else if ((r -= NA) < NB)   { row = 2066 + r / PITCH;     col = r % PITCH; }
        else if ((r -= NB) < NL)   { row = GY + r / 8;           col = r % 8; }
        else        { r -= NL;       row = GY + r / 142;          col = 2066 + r % 142; }
        base[row * PITCH + col] = 0.0f;
    }
}

// ---------------- pad (edge replicate) HWC -> planar padded interior ----------------
__global__ void swf_pad(const float* __restrict__ img) {
    int total = C_IMG * PH * PW;
    for (int i = blockIdx.x * blockDim.x + threadIdx.x; i < total;
         i += gridDim.x * blockDim.x) {
        int x = i % PW;
        int t = i / PW;
        int y = t % PH;
        int c = t / PH;
        int sy = y - RAD; sy = sy < 0 ? 0 : (sy > H_IMG - 1 ? H_IMG - 1 : sy);
        int sx = x - RAD; sx = sx < 0 ? 0 : (sx > W_IMG - 1 ? W_IMG - 1 : sx);
        g_U[0][c * PLANE + (y + GY) * PITCH + (x + GX)] =
            img[(sy * W_IMG + sx) * C_IMG + c];
    }
}

// ---------------- one side-window iteration ----------------
#define TH 30
#define TROWS (TH + 2*RAD)        // 40
#define TW 128
#define TCOLS 148                 // 37 float4; bank-friendly stride
#define TC4   (TCOLS/4)           // 37
#define NF4   (TROWS * TC4)       // 1480
#define H6W   138                 // 6 segments x 23 cols, fully covered

// Stage-3 vertical walk with lead sums. FULL=true: no per-row bounds check.
template<bool FULL>
__device__ __forceinline__ void walk(const float* __restrict__ hp,
                                     const float* __restrict__ hp5,
                                     const float* __restrict__ cp,
                                     float* __restrict__ Drow,
                                     int base, bool xok, int nvalid)
{
    const float i36 = 1.0f / 36.0f;
    const float i66 = 1.0f / 66.0f;

    float rHL[7], rHR[7], rCc[7];
    #pragma unroll
    for (int j = 0; j < 7; j++) {
        int row = base + j;
        rHL[j] = hp[row * H6W];
        rHR[j] = hp5[row * H6W];
        rCc[j] = cp[row * TCOLS];
    }

    float A  = rHL[0] + rHL[1] + rHL[2] + rHL[3] + rHL[4] + rHL[5];
    float B  = rHR[0] + rHR[1] + rHR[2] + rHR[3] + rHR[4] + rHR[5];
    float C6 = rCc[0] + rCc[1] + rCc[2] + rCc[3] + rCc[4] + rCc[5];
    float Dw = A + B - C6;

    float Ah[6], Bh[6], Dh[6];
    Ah[5] = A; Bh[5] = B; Dh[5] = Dw;

    // prologue j=6 (row already in ring)
    A  += rHL[6] - rHL[0];
    B  += rHR[6] - rHR[0];
    C6 += rCc[6] - rCc[0];
    Dw  = A + B - C6;
    Ah[0] = A; Bh[0] = B; Dh[0] = Dw;

    // prologue j=7..9
    #pragma unroll
    for (int j = 7; j <= 9; j++) {
        int row = base + j;
        float nHL = hp[row * H6W];
        float nHR = hp5[row * H6W];
        float nCc = cp[row * TCOLS];
        A  += nHL - rHL[(j - 6) % 7];
        B  += nHR - rHR[(j - 6) % 7];
        C6 += nCc - rCc[(j - 6) % 7];
        rHL[j % 7] = nHL; rHR[j % 7] = nHR; rCc[j % 7] = nCc;
        Dw = A + B - C6;
        Ah[j % 6] = A; Bh[j % 6] = B; Dh[j % 6] = Dw;
    }

    // main walk: ly = 0..TH/2-1, lead j = 10+ly
    #pragma unroll
    for (int ly = 0; ly < TH / 2; ly++) {
        const int j = 10 + ly;
        {
            int row = base + j;
            float nHL = hp[row * H6W];
            float nHR = hp5[row * H6W];
            float nCc = cp[row * TCOLS];
            A  += nHL - rHL[(j - 6) % 7];
            B  += nHR - rHR[(j - 6) % 7];
            C6 += nCc - rCc[(j - 6) % 7];
            rHL[j % 7] = nHL; rHR[j % 7] = nHR; rCc[j % 7] = nCc;
            Dw = A + B - C6;
        }

        const float uL = Ah[(j - 5) % 6];
        const float uR = Bh[(j - 5) % 6];
        const float uF = Dh[(j - 5) % 6];
        Ah[j % 6] = A; Bh[j % 6] = B; Dh[j % 6] = Dw;

        const float hL = rHL[(j - 5) % 7];
        const float hR = rHR[(j - 5) % 7];
        const float c0 = rCc[(j - 5) % 7];
        const float nc0 = -c0;

        const float fL = uL + A - hL;
        const float fR = uR + B - hR;

        // deltas, reference order [LL,LR,RL,RR,L*k,R*k,k*L,k*R]
        const float d0 = fmaf(uL, i36, nc0);
        const float d1 = fmaf(uR, i36, nc0);
        const float d2 = fmaf(A,  i36, nc0);
        const float d3 = fmaf(B,  i36, nc0);
        const float d4 = fmaf(uF, i66, nc0);
        const float d5 = fmaf(Dw, i66, nc0);
        const float d6 = fmaf(fL, i66, nc0);
        const float d7 = fmaf(fR, i66, nc0);

        // Tournament argmin, first-min-on-tie.
        float w01 = (fabsf(d1) < fabsf(d0)) ? d1 : d0;
        float a01 = fminf(fabsf(d1), fabsf(d0));
        float w23 = (fabsf(d3) < fabsf(d2)) ? d3 : d2;
        float a23 = fminf(fabsf(d3), fabsf(d2));
        float w45 = (fabsf(d5) < fabsf(d4)) ? d5 : d4;
        float a45 = fminf(fabsf(d5), fabsf(d4));
        float w67 = (fabsf(d7) < fabsf(d6)) ? d7 : d6;
        float a67 = fminf(fabsf(d7), fabsf(d6));

        float w03 = (a23 < a01) ? w23 : w01;
        float a03 = fminf(a23, a01);
        float w47 = (a67 < a45) ? w67 : w45;
        float a47 = fminf(a67, a45);

        float bd = (a47 < a03) ? w47 : w03;

        if (FULL) {
            if (xok) Drow[ly * PITCH] = c0 + bd;
        } else {
            if (xok && ly < nvalid) Drow[ly * PITCH] = c0 + bd;
        }
    }
}

__global__ __launch_bounds__(256)
void swf_iter(int s) {
    const float* __restrict__ S = g_U[s];
    float* __restrict__ Dst = g_U[s ^ 1];

    __shared__ float tile[TROWS * TCOLS];   // 40*148 floats
    __shared__ float h6[TROWS * H6W];       // 40*138 floats

    const int c  = blockIdx.z;
    const int x0 = blockIdx.x * TW;
    const int y0 = blockIdx.y * TH;
    const int t  = threadIdx.x;             // 0..255
    const float* __restrict__ Sp = S + c * PLANE;
    float* __restrict__ Dp = Dst + c * PLANE;

    // ---- Stage 1: unconditional float4 tile load (guards supply zeros) ----
    {
        const float4* __restrict__ Sp4 =
            (const float4*)(Sp + (y0 + 3) * PITCH + x0);
        float4* tile4 = (float4*)tile;
        #pragma unroll
        for (int k = 0; k < 6; k++) {
            int idx = t + k * 256;
            if (idx < NF4) {
                int r  = idx / TC4;
                int c4 = idx - r * TC4;
                tile4[r * TC4 + c4] = Sp4[r * (PITCH / 4) + c4];
            }
        }
    }
    __syncthreads();

    // ---- Stage 2: horizontal extended 6-sums, fully unrolled, LDS ring ----
    // h6[r][cc] = sum tile[r][cc+3 .. cc+8]; cc spans exactly [sx, sx+23).
    // 6 segments x 23 = 138 columns (133..137 harmless, in-bounds reads).
    if (t < TROWS * 6) {
        int r   = t / 6;
        int seg = t - r * 6;                 // 0..5
        int sx  = seg * 23;
        const float* trow = &tile[r * TCOLS + sx];
        float* hrow = &h6[r * H6W + sx];

        // leading-edge ring: e[k] holds trow-window trailing values
        float e0 = trow[3], e1 = trow[4], e2 = trow[5],
              e3 = trow[6], e4 = trow[7], e5 = trow[8];
        float sum = e0 + e1 + e2 + e3 + e4 + e5;
        hrow[0] = sum;
        float e[6] = {e0, e1, e2, e3, e4, e5};
        #pragma unroll
        for (int i = 1; i < 23; i++) {
            float nl = trow[i + 8];
            sum += nl - e[(i - 1) % 6];
            e[(i - 1) % 6] = nl;
            hrow[i] = sum;
        }
    }
    __syncthreads();

    // ---- Stage 3 ----
    const int lx   = t & 127;
    const int half = t >> 7;
    const int base = half * (TH / 2);        // 0 or 15
    const int gx   = x0 + lx;
    const bool xok = (gx < PW);

    const float* hp  = h6 + lx;
    const float* hp5 = h6 + lx + 5;
    const float* cp  = tile + lx + 8;
    float* Drow = Dp + (y0 + base + GY) * PITCH + gx + GX;

    const int row0 = y0 + base;
    if (row0 + TH / 2 <= PH) {
        walk<true>(hp, hp5, cp, Drow, base, xok, 0);
    } else {
        int nvalid = PH - row0;
        walk<false>(hp, hp5, cp, Drow, base, xok, nvalid);
    }
}

// ---------------- crop planar padded -> HWC output ----------------
__global__ void swf_crop(float* __restrict__ out) {
    int total = H_IMG * W_IMG * C_IMG;
    for (int i = blockIdx.x * blockDim.x + threadIdx.x; i < total;
         i += gridDim.x * blockDim.x) {
        int c = i % C_IMG;
        int t = i / C_IMG;
        int x = t % W_IMG;
        int y = t / W_IMG;
        out[i] = g_U[0][c * PLANE + (y + RAD + GY) * PITCH + (x + RAD + GX)];
    }
}

extern "C" void kernel_launch(void* const* d_in, const int* in_sizes, int n_in,
                              void* d_out, int out_size) {
    const float* img = (const float*)d_in[0];   // (2048,2048,3) f32; d_in[1] hardcoded
    float* out = (float*)d_out;

    {
        dim3 grid(512, 6, 1);
        swf_guard_zero<<<grid, 256>>>();
    }
    {
        int total = C_IMG * PH * PW;
        int blocks = (total + 255) / 256;
        if (blocks > 65535) blocks = 65535;
        swf_pad<<<blocks, 256>>>(img);
    }

    dim3 block(256, 1, 1);
    dim3 grid((PW + TW - 1) / TW, (PH + TH - 1) / TH, C_IMG);
    for (int i = 0; i < NITER; i++) {
        swf_iter<<<grid, block>>>(i & 1);
    }

    {
        int total = H_IMG * W_IMG * C_IMG;
        int blocks = (total + 255) / 256;
        if (blocks > 65535) blocks = 65535;
        swf_crop<<<blocks, 256>>>(out);
    }
}

// round 10
// speedup vs baseline: 1.3268x; 1.0231x over previous
#include <cuda_runtime.h>
#include <cuda_bf16.h>

// ---------------- problem constants ----------------
#define H_IMG   2048
#define W_IMG   2048
#define C_IMG   3
#define RAD     5
#define NITER   10
#define PH      (H_IMG + 2*RAD)   // 2058
#define PW      (W_IMG + 2*RAD)   // 2058

// Guarded buffer layout: interior pixel (y,x) lives at row y+GY, col x+GX.
// Guard bands stay zero so the iteration kernel loads float4 with NO bounds checks.
#define GY      8
#define GX      8
#define PROWS   2104
#define PITCH   2208
#define PLANE   (PROWS * PITCH)
#define BUFSZ   (C_IMG * PLANE)

__device__ float g_U[2][BUFSZ];

// ---------------- zero all guard bands of both buffers ----------------
#define NA (8 * PITCH)
#define NB (38 * PITCH)
#define NL (PH * 8)
#define NR (PH * 142)
#define NGUARD (NA + NB + NL + NR)

__global__ void swf_guard_zero() {
    int plane = blockIdx.y;            // 0..5 : b*3 + c
    int b = plane / 3;
    int c = plane - b * 3;
    float* base = g_U[b] + c * PLANE;
    for (int i = blockIdx.x * blockDim.x + threadIdx.x; i < NGUARD;
         i += gridDim.x * blockDim.x) {
        int row, col, r = i;
        if (r < NA)                { row = r / PITCH;            col = r % PITCH; }
        else if ((r -= NA) < NB)   { row = 2066 + r / PITCH;     col = r % PITCH; }
        else if ((r -= NB) < NL)   { row = GY + r / 8;           col = r % 8; }
        else        { r -= NL;       row = GY + r / 142;          col = 2066 + r % 142; }
        base[row * PITCH + col] = 0.0f;
    }
}

// ---------------- pad (edge replicate) HWC -> planar padded interior ----------------
__global__ void swf_pad(const float* __restrict__ img) {
    int total = C_IMG * PH * PW;
    for (int i = blockIdx.x * blockDim.x + threadIdx.x; i < total;
         i += gridDim.x * blockDim.x) {
        int x = i % PW;
        int t = i / PW;
        int y = t % PH;
        int c = t / PH;
        int sy = y - RAD; sy = sy < 0 ? 0 : (sy > H_IMG - 1 ? H_IMG - 1 : sy);
        int sx = x - RAD; sx = sx < 0 ? 0 : (sx > W_IMG - 1 ? W_IMG - 1 : sx);
        g_U[0][c * PLANE + (y + GY) * PITCH + (x + GX)] =
            img[(sy * W_IMG + sx) * C_IMG + c];
    }
}

// ---------------- one side-window iteration ----------------
#define TH 30
#define TROWS (TH + 2*RAD)        // 40
#define TW 128
#define TCOLS 148                 // 37 float4; bank-friendly stride
#define TC4   (TCOLS/4)           // 37
#define NF4   (TROWS * TC4)       // 1480
#define H6W   138                 // 6 segments x 23 cols, fully covered

// Stage-3 vertical walk with lead sums. FULL=true: no per-row bounds check.
template<bool FULL>
__device__ __forceinline__ void walk(const float* __restrict__ hp,
                                     const float* __restrict__ hp5,
                                     const float* __restrict__ cp,
                                     float* __restrict__ Drow,
                                     int base, bool xok, int nvalid)
{
    const float i36 = 1.0f / 36.0f;
    const float i66 = 1.0f / 66.0f;

    float rHL[7], rHR[7], rCc[7];
    #pragma unroll
    for (int j = 0; j < 7; j++) {
        int row = base + j;
        rHL[j] = hp[row * H6W];
        rHR[j] = hp5[row * H6W];
        rCc[j] = cp[row * TCOLS];
    }

    float A  = rHL[0] + rHL[1] + rHL[2] + rHL[3] + rHL[4] + rHL[5];
    float B  = rHR[0] + rHR[1] + rHR[2] + rHR[3] + rHR[4] + rHR[5];
    float C6 = rCc[0] + rCc[1] + rCc[2] + rCc[3] + rCc[4] + rCc[5];
    float Dw = A + B - C6;

    float Ah[6], Bh[6], Dh[6];
    Ah[5] = A; Bh[5] = B; Dh[5] = Dw;

    // prologue j=6 (row already in ring)
    A  += rHL[6] - rHL[0];
    B  += rHR[6] - rHR[0];
    C6 += rCc[6] - rCc[0];
    Dw  = A + B - C6;
    Ah[0] = A; Bh[0] = B; Dh[0] = Dw;

    // prologue j=7..9
    #pragma unroll
    for (int j = 7; j <= 9; j++) {
        int row = base + j;
        float nHL = hp[row * H6W];
        float nHR = hp5[row * H6W];
        float nCc = cp[row * TCOLS];
        A  += nHL - rHL[(j - 6) % 7];
        B  += nHR - rHR[(j - 6) % 7];
        C6 += nCc - rCc[(j - 6) % 7];
        rHL[j % 7] = nHL; rHR[j % 7] = nHR; rCc[j % 7] = nCc;
        Dw = A + B - C6;
        Ah[j % 6] = A; Bh[j % 6] = B; Dh[j % 6] = Dw;
    }

    // main walk: ly = 0..TH/2-1, lead j = 10+ly
    #pragma unroll
    for (int ly = 0; ly < TH / 2; ly++) {
        const int j = 10 + ly;
        {
            int row = base + j;
            float nHL = hp[row * H6W];
            float nHR = hp5[row * H6W];
            float nCc = cp[row * TCOLS];
            A  += nHL - rHL[(j - 6) % 7];
            B  += nHR - rHR[(j - 6) % 7];
            C6 += nCc - rCc[(j - 6) % 7];
            rHL[j % 7] = nHL; rHR[j % 7] = nHR; rCc[j % 7] = nCc;
            Dw = A + B - C6;
        }

        const float uL = Ah[(j - 5) % 6];
        const float uR = Bh[(j - 5) % 6];
        const float uF = Dh[(j - 5) % 6];
        Ah[j % 6] = A; Bh[j % 6] = B; Dh[j % 6] = Dw;

        const float hL = rHL[(j - 5) % 7];
        const float hR = rHR[(j - 5) % 7];
        const float c0 = rCc[(j - 5) % 7];
        const float nc0 = -c0;

        const float fL = uL + A - hL;
        const float fR = uR + B - hR;

        // deltas, reference order [LL,LR,RL,RR,L*k,R*k,k*L,k*R]
        const float d0 = fmaf(uL, i36, nc0);
        const float d1 = fmaf(uR, i36, nc0);
        const float d2 = fmaf(A,  i36, nc0);
        const float d3 = fmaf(B,  i36, nc0);
        const float d4 = fmaf(uF, i66, nc0);
        const float d5 = fmaf(Dw, i66, nc0);
        const float d6 = fmaf(fL, i66, nc0);
        const float d7 = fmaf(fR, i66, nc0);

        // Tournament argmin, first-min-on-tie. |selected| IS the running min,
        // and |.| is a free operand modifier on FSETP -> FSETP+FSEL per node.
        const float w01 = (fabsf(d1) < fabsf(d0)) ? d1 : d0;
        const float w23 = (fabsf(d3) < fabsf(d2)) ? d3 : d2;
        const float w45 = (fabsf(d5) < fabsf(d4)) ? d5 : d4;
        const float w67 = (fabsf(d7) < fabsf(d6)) ? d7 : d6;
        const float w03 = (fabsf(w23) < fabsf(w01)) ? w23 : w01;
        const float w47 = (fabsf(w67) < fabsf(w45)) ? w67 : w45;
        const float bd  = (fabsf(w47) < fabsf(w03)) ? w47 : w03;

        if (FULL) {
            if (xok) Drow[ly * PITCH] = c0 + bd;
        } else {
            if (xok && ly < nvalid) Drow[ly * PITCH] = c0 + bd;
        }
    }
}

__global__ __launch_bounds__(256)
void swf_iter(int s) {
    const float* __restrict__ S = g_U[s];
    float* __restrict__ Dst = g_U[s ^ 1];

    __shared__ float tile[TROWS * TCOLS];   // 40*148 floats
    __shared__ float h6[TROWS * H6W];       // 40*138 floats

    const int c  = blockIdx.z;
    const int x0 = blockIdx.x * TW;
    const int y0 = blockIdx.y * TH;
    const int t  = threadIdx.x;             // 0..255
    const float* __restrict__ Sp = S + c * PLANE;
    float* __restrict__ Dp = Dst + c * PLANE;

    // ---- Stage 1: unconditional float4 tile load (guards supply zeros) ----
    {
        const float4* __restrict__ Sp4 =
            (const float4*)(Sp + (y0 + 3) * PITCH + x0);
        float4* tile4 = (float4*)tile;
        #pragma unroll
        for (int k = 0; k < 6; k++) {
            int idx = t + k * 256;
            if (idx < NF4) {
                int r  = idx / TC4;
                int c4 = idx - r * TC4;
                tile4[r * TC4 + c4] = Sp4[r * (PITCH / 4) + c4];
            }
        }
    }
    __syncthreads();

    // ---- Stage 2: horizontal extended 6-sums, fully unrolled, LDS ring ----
    if (t < TROWS * 6) {
        int r   = t / 6;
        int seg = t - r * 6;                 // 0..5
        int sx  = seg * 23;
        const float* trow = &tile[r * TCOLS + sx];
        float* hrow = &h6[r * H6W + sx];

        float e0 = trow[3], e1 = trow[4], e2 = trow[5],
              e3 = trow[6], e4 = trow[7], e5 = trow[8];
        float sum = e0 + e1 + e2 + e3 + e4 + e5;
        hrow[0] = sum;
        float e[6] = {e0, e1, e2, e3, e4, e5};
        #pragma unroll
        for (int i = 1; i < 23; i++) {
            float nl = trow[i + 8];
            sum += nl - e[(i - 1) % 6];
            e[(i - 1) % 6] = nl;
            hrow[i] = sum;
        }
    }
    __syncthreads();

    // ---- Stage 3 ----
    const int lx   = t & 127;
    const int half = t >> 7;
    const int base = half * (TH / 2);        // 0 or 15
    const int gx   = x0 + lx;
    const bool xok = (gx < PW);

    const float* hp  = h6 + lx;
    const float* hp5 = h6 + lx + 5;
    const float* cp  = tile + lx + 8;
    float* Drow = Dp + (y0 + base + GY) * PITCH + gx + GX;

    const int row0 = y0 + base;
    if (row0 + TH / 2 <= PH) {
        walk<true>(hp, hp5, cp, Drow, base, xok, 0);
    } else {
        int nvalid = PH - row0;
        walk<false>(hp, hp5, cp, Drow, base, xok, nvalid);
    }
}

// ---------------- crop planar padded -> HWC output ----------------
__global__ void swf_crop(float* __restrict__ out) {
    int total = H_IMG * W_IMG * C_IMG;
    for (int i = blockIdx.x * blockDim.x + threadIdx.x; i < total;
         i += gridDim.x * blockDim.x) {
        int c = i % C_IMG;
        int t = i / C_IMG;
        int x = t % W_IMG;
        int y = t / W_IMG;
        out[i] = g_U[0][c * PLANE + (y + RAD + GY) * PITCH + (x + RAD + GX)];
    }
}

extern "C" void kernel_launch(void* const* d_in, const int* in_sizes, int n_in,
                              void* d_out, int out_size) {
    const float* img = (const float*)d_in[0];   // (2048,2048,3) f32; d_in[1] hardcoded
    float* out = (float*)d_out;

    {
        dim3 grid(512, 6, 1);
        swf_guard_zero<<<grid, 256>>>();
    }
    {
        int total = C_IMG * PH * PW;
        int blocks = (total + 255) / 256;
        if (blocks > 65535) blocks = 65535;
        swf_pad<<<blocks, 256>>>(img);
    }

    dim3 block(256, 1, 1);
    dim3 grid((PW + TW - 1) / TW, (PH + TH - 1) / TH, C_IMG);
    for (int i = 0; i < NITER; i++) {
        swf_iter<<<grid, block>>>(i & 1);
    }

    {
        int total = H_IMG * W_IMG * C_IMG;
        int blocks = (total + 255) / 256;
        if (blocks > 65535) blocks = 65535;
        swf_crop<<<blocks, 256>>>(out);
    }
}

// round 11
// speedup vs baseline: 1.4597x; 1.1001x over previous
#include <cuda_runtime.h>
#include <cuda_bf16.h>

// ---------------- problem constants ----------------
#define H_IMG   2048
#define W_IMG   2048
#define C_IMG   3
#define RAD     5
#define NITER   10
#define PH      (H_IMG + 2*RAD)   // 2058
#define PW      (W_IMG + 2*RAD)   // 2058

// Guarded buffer layout: interior pixel (y,x) lives at row y+GY, col x+GX.
// Guard bands stay zero so mid iterations load float4 with NO bounds checks.
#define GY      8
#define GX      8
#define PROWS   2104
#define PITCH   2208
#define PLANE   (PROWS * PITCH)
#define BUFSZ   (C_IMG * PLANE)

__device__ float g_U[2][BUFSZ];

// ---------------- zero all guard bands of both buffers ----------------
#define NA (8 * PITCH)
#define NB (38 * PITCH)
#define NL (PH * 8)
#define NR (PH * 142)
#define NGUARD (NA + NB + NL + NR)

__global__ void swf_guard_zero() {
    int plane = blockIdx.y;            // 0..5 : b*3 + c
    int b = plane / 3;
    int c = plane - b * 3;
    float* base = g_U[b] + c * PLANE;
    for (int i = blockIdx.x * blockDim.x + threadIdx.x; i < NGUARD;
         i += gridDim.x * blockDim.x) {
        int row, col, r = i;
        if (r < NA)                { row = r / PITCH;            col = r % PITCH; }
        else if ((r -= NA) < NB)   { row = 2066 + r / PITCH;     col = r % PITCH; }
        else if ((r -= NB) < NL)   { row = GY + r / 8;           col = r % 8; }
        else        { r -= NL;       row = GY + r / 142;          col = 2066 + r % 142; }
        base[row * PITCH + col] = 0.0f;
    }
}

// ---------------- one side-window iteration (3 modes) ----------------
#define TH 30
#define TROWS (TH + 2*RAD)        // 40
#define TW 128
#define TCOLS 148                 // 37 float4; bank-friendly stride
#define TC4   (TCOLS/4)           // 37
#define NF4   (TROWS * TC4)       // 1480
#define H6W   138                 // 6 segments x 23 cols, fully covered

#define MODE_FIRST 0
#define MODE_MID   1
#define MODE_LAST  2

// Stage-3 vertical walk with lead sums.
// FULL=true: every row stores (only xok checked). Otherwise rows [lo,hi) store.
// ptr/stride define the destination row walk.
template<bool FULL>
__device__ __forceinline__ void walk(const float* __restrict__ hp,
                                     const float* __restrict__ hp5,
                                     const float* __restrict__ cp,
                                     float* __restrict__ ptr, int stride,
                                     int base, bool xok, int lo, int hi)
{
    const float i36 = 1.0f / 36.0f;
    const float i66 = 1.0f / 66.0f;

    float rHL[7], rHR[7], rCc[7];
    #pragma unroll
    for (int j = 0; j < 7; j++) {
        int row = base + j;
        rHL[j] = hp[row * H6W];
        rHR[j] = hp5[row * H6W];
        rCc[j] = cp[row * TCOLS];
    }

    float A  = rHL[0] + rHL[1] + rHL[2] + rHL[3] + rHL[4] + rHL[5];
    float B  = rHR[0] + rHR[1] + rHR[2] + rHR[3] + rHR[4] + rHR[5];
    float C6 = rCc[0] + rCc[1] + rCc[2] + rCc[3] + rCc[4] + rCc[5];
    float Dw = A + B - C6;

    float Ah[6], Bh[6], Dh[6];
    Ah[5] = A; Bh[5] = B; Dh[5] = Dw;

    // prologue j=6 (row already in ring)
    A  += rHL[6] - rHL[0];
    B  += rHR[6] - rHR[0];
    C6 += rCc[6] - rCc[0];
    Dw  = A + B - C6;
    Ah[0] = A; Bh[0] = B; Dh[0] = Dw;

    // prologue j=7..9
    #pragma unroll
    for (int j = 7; j <= 9; j++) {
        int row = base + j;
        float nHL = hp[row * H6W];
        float nHR = hp5[row * H6W];
        float nCc = cp[row * TCOLS];
        A  += nHL - rHL[(j - 6) % 7];
        B  += nHR - rHR[(j - 6) % 7];
        C6 += nCc - rCc[(j - 6) % 7];
        rHL[j % 7] = nHL; rHR[j % 7] = nHR; rCc[j % 7] = nCc;
        Dw = A + B - C6;
        Ah[j % 6] = A; Bh[j % 6] = B; Dh[j % 6] = Dw;
    }

    // main walk: ly = 0..TH/2-1, lead j = 10+ly
    #pragma unroll
    for (int ly = 0; ly < TH / 2; ly++) {
        const int j = 10 + ly;
        {
            int row = base + j;
            float nHL = hp[row * H6W];
            float nHR = hp5[row * H6W];
            float nCc = cp[row * TCOLS];
            A  += nHL - rHL[(j - 6) % 7];
            B  += nHR - rHR[(j - 6) % 7];
            C6 += nCc - rCc[(j - 6) % 7];
            rHL[j % 7] = nHL; rHR[j % 7] = nHR; rCc[j % 7] = nCc;
            Dw = A + B - C6;
        }

        const float uL = Ah[(j - 5) % 6];
        const float uR = Bh[(j - 5) % 6];
        const float uF = Dh[(j - 5) % 6];
        Ah[j % 6] = A; Bh[j % 6] = B; Dh[j % 6] = Dw;

        const float hL = rHL[(j - 5) % 7];
        const float hR = rHR[(j - 5) % 7];
        const float c0 = rCc[(j - 5) % 7];
        const float nc0 = -c0;

        const float fL = uL + A - hL;
        const float fR = uR + B - hR;

        // deltas, reference order [LL,LR,RL,RR,L*k,R*k,k*L,k*R]
        const float d0 = fmaf(uL, i36, nc0);
        const float d1 = fmaf(uR, i36, nc0);
        const float d2 = fmaf(A,  i36, nc0);
        const float d3 = fmaf(B,  i36, nc0);
        const float d4 = fmaf(uF, i66, nc0);
        const float d5 = fmaf(Dw, i66, nc0);
        const float d6 = fmaf(fL, i66, nc0);
        const float d7 = fmaf(fR, i66, nc0);

        // Tournament argmin, first-min-on-tie; |.| free on FSETP operands.
        const float w01 = (fabsf(d1) < fabsf(d0)) ? d1 : d0;
        const float w23 = (fabsf(d3) < fabsf(d2)) ? d3 : d2;
        const float w45 = (fabsf(d5) < fabsf(d4)) ? d5 : d4;
        const float w67 = (fabsf(d7) < fabsf(d6)) ? d7 : d6;
        const float w03 = (fabsf(w23) < fabsf(w01)) ? w23 : w01;
        const float w47 = (fabsf(w67) < fabsf(w45)) ? w67 : w45;
        const float bd  = (fabsf(w47) < fabsf(w03)) ? w47 : w03;

        if (FULL) {
            if (xok) ptr[ly * stride] = c0 + bd;
        } else {
            if (xok && ly >= lo && ly < hi) ptr[ly * stride] = c0 + bd;
        }
    }
}

template<int MODE>
__global__ __launch_bounds__(256)
void swf_iter(const float* __restrict__ img, float* __restrict__ out, int s) {
    float* __restrict__ Dst = (MODE == MODE_FIRST) ? g_U[0] : g_U[s ^ 1];

    __shared__ float tile[TROWS * TCOLS];   // 40*148 floats
    __shared__ float h6[TROWS * H6W];       // 40*138 floats

    const int c  = blockIdx.z;
    const int x0 = blockIdx.x * TW;
    const int y0 = blockIdx.y * TH;
    const int t  = threadIdx.x;             // 0..255
    float* __restrict__ Dp = Dst + c * PLANE;

    // ---- Stage 1 ----
    if (MODE == MODE_FIRST) {
        // Gather directly from HWC img with edge replicate; zero outside the
        // padded field. Scalar + clamped, paid only on iteration 0.
        for (int idx = t; idx < TROWS * TCOLS; idx += 256) {
            int r   = idx / TCOLS;
            int lxc = idx - r * TCOLS;
            int y = y0 + r - 5;             // padded-field row
            int x = x0 + lxc - 8;           // padded-field col
            float v = 0.0f;
            if (y >= 0 && y < PH && x >= 0 && x < PW) {
                int sy = y - RAD; sy = sy < 0 ? 0 : (sy > H_IMG - 1 ? H_IMG - 1 : sy);
                int sx = x - RAD; sx = sx < 0 ? 0 : (sx > W_IMG - 1 ? W_IMG - 1 : sx);
                v = img[(sy * W_IMG + sx) * C_IMG + c];
            }
            tile[idx] = v;
        }
    } else {
        // Unconditional float4 tile load (guards supply zeros).
        const float* __restrict__ Sp = g_U[s] + c * PLANE;
        const float4* __restrict__ Sp4 =
            (const float4*)(Sp + (y0 + 3) * PITCH + x0);
        float4* tile4 = (float4*)tile;
        #pragma unroll
        for (int k = 0; k < 6; k++) {
            int idx = t + k * 256;
            if (idx < NF4) {
                int r  = idx / TC4;
                int c4 = idx - r * TC4;
                tile4[r * TC4 + c4] = Sp4[r * (PITCH / 4) + c4];
            }
        }
    }
    __syncthreads();

    // ---- Stage 2: horizontal extended 6-sums, fully unrolled, LDS ring ----
    if (t < TROWS * 6) {
        int r   = t / 6;
        int seg = t - r * 6;                 // 0..5
        int sx  = seg * 23;
        const float* trow = &tile[r * TCOLS + sx];
        float* hrow = &h6[r * H6W + sx];

        float e0 = trow[3], e1 = trow[4], e2 = trow[5],
              e3 = trow[6], e4 = trow[7], e5 = trow[8];
        float sum = e0 + e1 + e2 + e3 + e4 + e5;
        hrow[0] = sum;
        float e[6] = {e0, e1, e2, e3, e4, e5};
        #pragma unroll
        for (int i = 1; i < 23; i++) {
            float nl = trow[i + 8];
            sum += nl - e[(i - 1) % 6];
            e[(i - 1) % 6] = nl;
            hrow[i] = sum;
        }
    }
    __syncthreads();

    // ---- Stage 3 ----
    const int lx   = t & 127;
    const int half = t >> 7;
    const int base = half * (TH / 2);        // 0 or 15
    const int gx   = x0 + lx;

    const float* hp  = h6 + lx;
    const float* hp5 = h6 + lx + 5;
    const float* cp  = tile + lx + 8;

    const int row0 = y0 + base;              // first output row (padded field)

    if (MODE == MODE_LAST) {
        // Write cropped HWC output directly: valid gy,gx in [5, 2052].
        const bool xok = (gx >= RAD) && (gx < PW - RAD);
        int lo = RAD - row0;      if (lo < 0) lo = 0;
        int hi = (PH - RAD) - row0; if (hi > TH / 2) hi = TH / 2;
        float* optr = out + (((row0 - RAD) * W_IMG) + (gx - RAD)) * C_IMG + c;
        walk<false>(hp, hp5, cp, optr, W_IMG * C_IMG, base, xok, lo, hi);
    } else {
        const bool xok = (gx < PW);
        float* Drow = Dp + (row0 + GY) * PITCH + gx + GX;
        if (row0 + TH / 2 <= PH) {
            walk<true>(hp, hp5, cp, Drow, PITCH, base, xok, 0, TH / 2);
        } else {
            int nvalid = PH - row0;
            walk<false>(hp, hp5, cp, Drow, PITCH, base, xok, 0, nvalid);
        }
    }
}

extern "C" void kernel_launch(void* const* d_in, const int* in_sizes, int n_in,
                              void* d_out, int out_size) {
    const float* img = (const float*)d_in[0];   // (2048,2048,3) f32; d_in[1] hardcoded
    float* out = (float*)d_out;

    {
        dim3 grid(512, 6, 1);
        swf_guard_zero<<<grid, 256>>>();
    }

    dim3 block(256, 1, 1);
    dim3 grid((PW + TW - 1) / TW, (PH + TH - 1) / TH, C_IMG);

    // iter 0: img -> g_U[0]
    swf_iter<MODE_FIRST><<<grid, block>>>(img, out, 0);
    // iters 1..8: g_U[(i-1)&1] -> g_U[i&1]
    for (int i = 1; i <= 8; i++) {
        swf_iter<MODE_MID><<<grid, block>>>(img, out, (i - 1) & 1);
    }
    // iter 9: g_U[0] -> out (cropped HWC)
    swf_iter<MODE_LAST><<<grid, block>>>(img, out, 0);
}